// round 13
// baseline (speedup 1.0000x reference)
#include <cuda_runtime.h>
#include <cuda_bf16.h>

// Problem constants
#define BB 8
#define SS 2048
#define FF 256
#define HH 8
#define DD 64
#define PROJ 512            // HH*DD
#define NSC 32              // s-chunks (64 rows each)
#define SCH 64              // rows per chunk

// Scratch (device globals — no allocation allowed)
__device__ float g_p[BB * HH * FF];             // p[b][h][f] = Wk_h @ q_last
__device__ float g_cm[BB * HH * NSC * 2];       // per-chunk (max, sumexp)
__device__ float g_yc[BB * NSC * HH * FF];      // unnormalized chunk sums (2MB)
__device__ float g_op[BB * 16 * FF];            // partial outputs per (h,fh)

// Producer/consumer counters (replay-safe: each is reset by the OTHER kernel,
// across a kernel boundary from every use).
__device__ unsigned int g_pcnt[BB];             // prep-done count (K1); reset in K2
__device__ unsigned int g_pcnt2[BB];            // proj-done count (K2); reset in K1

// =========================================================================
// K1: 256 blocks (b, chunk) x 256 threads.
//   chunk<8 : prep for (b, h=chunk): q_h = x_last @ Wq_h; p = Wk_h @ q_h
//             then atomicAdd(g_pcnt[b]).
//   chunk==8: t0 resets g_pcnt2[b] for this replay's K2.
//   all     : spin until g_pcnt[b]==8, then flash over (b, chunk):
//             scores -> local (m,d) -> weights -> weighted x sum -> g_yc.
// __launch_bounds__(256,2): <=128 regs, 2 blocks/SM -> all 256 co-resident.
// =========================================================================
__global__ __launch_bounds__(256, 2)
void k_main(const float* __restrict__ x,
            const float* __restrict__ Wq,
            const float* __restrict__ Wk) {
    int blk = blockIdx.x;
    int b = blk >> 5;
    int chunk = blk & 31;
    int t = threadIdx.x;
    int warp = t >> 5, lane = t & 31;

    __shared__ float xs[FF];
    __shared__ float qred[4][DD];
    __shared__ float qs[DD];
    __shared__ float ps[HH * FF];       // 8KB
    __shared__ float sbuf[HH][SCH];     // 2KB
    __shared__ float ws[HH][SCH];       // 2KB
    __shared__ float mh[HH];

    // ---------------- prep: blocks with chunk < 8 --------------------------
    if (chunk < HH) {
        int h = chunk;
        if (t < FF) xs[t] = x[((size_t)b * SS + (SS - 1)) * FF + t];
        __syncthreads();

        {   // q_h[d]: 256 threads = 64 d x 4 f-parts of 64; batched loads
            int d = t & 63, part = t >> 6;
            const float* wq = Wq + (size_t)(part * 64) * PROJ + h * DD + d;
            const float* xf = xs + part * 64;
            float a = 0.f;
            #pragma unroll
            for (int g = 0; g < 4; ++g) {
                float w[16];
                #pragma unroll
                for (int i = 0; i < 16; ++i) w[i] = wq[(size_t)(g * 16 + i) * PROJ];
                #pragma unroll
                for (int i = 0; i < 16; ++i) a += xf[g * 16 + i] * w[i];
            }
            qred[part][d] = a;
        }
        __syncthreads();
        if (t < DD) qs[t] = qred[0][t] + qred[1][t] + qred[2][t] + qred[3][t];
        __syncthreads();

        {   // p[f]: one thread per f; contiguous 256B Wk row (16 float4, MLP 16)
            int f = t;
            const float4* wk4 = (const float4*)(Wk + (size_t)f * PROJ + h * DD);
            const float4* q4 = (const float4*)qs;
            float4 w[16];
            #pragma unroll
            for (int i = 0; i < 16; ++i) w[i] = wk4[i];
            float a = 0.f;
            #pragma unroll
            for (int i = 0; i < 16; ++i) {
                float4 q = q4[i];
                a += w[i].x * q.x + w[i].y * q.y + w[i].z * q.z + w[i].w * q.w;
            }
            g_p[(b * HH + h) * FF + f] = a;
        }
        __syncthreads();
        if (t == 0) {
            __threadfence();
            atomicAdd(&g_pcnt[b], 1u);
        }
    }

    // reset K2's counter for this replay (no K1 reader; K2 runs after K1)
    if (chunk == 8 && t == 0) g_pcnt2[b] = 0u;

    // ---------------- wait for this b's prep to finish ---------------------
    if (t == 0) {
        while (((volatile unsigned int*)g_pcnt)[b] < 8u) { }
    }
    __syncthreads();

    // ---------------- flash over (b, chunk) --------------------------------
    for (int i = t; i < HH * FF; i += 256) ps[i] = g_p[b * HH * FF + i];
    __syncthreads();

    const float4* ps4 = (const float4*)ps;
    const float4* xr_base = (const float4*)(x + ((size_t)b * SS + chunk * SCH) * FF);

    // Phase A: scores (8 warps x 4 rows x 2 iterations)
    #pragma unroll
    for (int it = 0; it < 2; ++it) {
        int r0 = it * 32 + warp * 4;
        const float4* xr = xr_base + (size_t)r0 * 64;

        float4 a[4], c[4];
        #pragma unroll
        for (int r = 0; r < 4; ++r) {
            a[r] = xr[r * 64 + lane];
            c[r] = xr[r * 64 + 32 + lane];
        }

        #pragma unroll
        for (int r = 0; r < 4; ++r) {
            float dot[HH];
            #pragma unroll
            for (int h = 0; h < HH; ++h) {
                float4 pa = ps4[h * 64 + lane];
                float4 pc = ps4[h * 64 + 32 + lane];
                dot[h] = a[r].x * pa.x + a[r].y * pa.y + a[r].z * pa.z + a[r].w * pa.w
                       + c[r].x * pc.x + c[r].y * pc.y + c[r].z * pc.z + c[r].w * pc.w;
            }
            #pragma unroll
            for (int h = 0; h < HH; ++h) {
                #pragma unroll
                for (int o = 16; o; o >>= 1)
                    dot[h] += __shfl_xor_sync(0xFFFFFFFFu, dot[h], o);
            }
            if (lane == 0) {
                #pragma unroll
                for (int h = 0; h < HH; ++h)
                    sbuf[h][r0 + r] = dot[h] * 0.125f;
            }
        }
    }
    __syncthreads();

    // local stats: warp h handles head h
    if (warp < HH) {
        int h = warp;
        float v0 = sbuf[h][lane], v1 = sbuf[h][lane + 32];
        float m = fmaxf(v0, v1);
        #pragma unroll
        for (int o = 16; o; o >>= 1) m = fmaxf(m, __shfl_xor_sync(0xFFFFFFFFu, m, o));
        float s = __expf(v0 - m) + __expf(v1 - m);
        #pragma unroll
        for (int o = 16; o; o >>= 1) s += __shfl_xor_sync(0xFFFFFFFFu, s, o);
        if (lane == 0) {
            int idx = ((b * HH + h) * NSC + chunk) * 2;
            g_cm[idx] = m;
            g_cm[idx + 1] = s;
            mh[h] = m;
        }
    }
    __syncthreads();

    // unnormalized weights
    #pragma unroll
    for (int i = 0; i < 2; ++i) {
        int e = t + i * 256;
        int h = e >> 6, s = e & 63;
        ws[h][s] = __expf(sbuf[h][s] - mh[h]);
    }
    __syncthreads();

    // Phase B: weighted sum (x hits L1); head-pair per thread
    {
        int f4 = t & 63, hp = t >> 6;
        int h0 = hp * 2;
        float4 a0 = make_float4(0.f, 0.f, 0.f, 0.f);
        float4 a1 = make_float4(0.f, 0.f, 0.f, 0.f);

        #pragma unroll 4
        for (int s = 0; s < SCH; ++s) {
            float4 xv = xr_base[(size_t)s * 64 + f4];
            float w0 = ws[h0][s], w1 = ws[h0 + 1][s];
            a0.x += w0 * xv.x; a0.y += w0 * xv.y; a0.z += w0 * xv.z; a0.w += w0 * xv.w;
            a1.x += w1 * xv.x; a1.y += w1 * xv.y; a1.z += w1 * xv.z; a1.w += w1 * xv.w;
        }

        float4* out4 = (float4*)(g_yc + ((size_t)(b * NSC + chunk)) * (HH * FF));
        out4[h0 * 64 + f4] = a0;
        out4[(h0 + 1) * 64 + f4] = a1;
    }
}

// =========================================================================
// K2: 128 blocks (b, h, fh) x 512 threads.
//   chunk-combine (softmax normalize) -> y_half -> @Wv_half -> attn_s[64]
//   -> @Wo (h's 64 rows) -> 256-wide partial -> g_op.
//   Last block per b (atomic count == 15) sums 16 partials + bias -> out.
//   Also resets g_pcnt[b] for the next replay's K1.
// =========================================================================
__global__ void k_proj(const float* __restrict__ Wv,
                       const float* __restrict__ Wo,
                       const float* __restrict__ bo,
                       float* __restrict__ out) {
    int blk = blockIdx.x;
    int b = blk >> 4;
    int h = (blk >> 1) & 7;
    int fh = blk & 1;
    int t = threadIdx.x;
    __shared__ float scales[NSC];
    __shared__ float stats[1];
    __shared__ float red[3][128];
    __shared__ float ys[128];
    __shared__ float ared[8][DD];
    __shared__ float attn_s[DD];
    __shared__ float4 red4[7][64];      // 7KB
    __shared__ int isLast;

    // reset K1's counter for next replay (no reader in this kernel)
    if (h == 0 && fh == 0 && t == 0) g_pcnt[b] = 0u;

    if (t < 32) {   // warp 0: global stats + per-chunk scales
        const float* cm = g_cm + (size_t)(b * HH + h) * NSC * 2;
        float m = cm[t * 2], d = cm[t * 2 + 1];
        float M = m;
        #pragma unroll
        for (int o = 16; o; o >>= 1) M = fmaxf(M, __shfl_xor_sync(0xFFFFFFFFu, M, o));
        float e = __expf(m - M);
        scales[t] = e;
        float ds = d * e;
        #pragma unroll
        for (int o = 16; o; o >>= 1) ds += __shfl_xor_sync(0xFFFFFFFFu, ds, o);
        if (t == 0) stats[0] = 1.f / ds;
    }
    __syncthreads();
    float invD = stats[0];

    {   // y-half: 512 threads = 128 f x 4 chunk-groups of 8; batched loads
        int f = t & 127, cg = t >> 7;
        const float* pp = g_yc + ((size_t)(b * NSC + cg * 8) * HH + h) * FF + fh * 128 + f;
        float v[8];
        #pragma unroll
        for (int c = 0; c < 8; ++c) v[c] = pp[(size_t)c * (HH * FF)];
        float s = 0.f;
        #pragma unroll
        for (int c = 0; c < 8; ++c) s += scales[cg * 8 + c] * v[c];
        if (cg > 0) red[cg - 1][f] = s;
        __syncthreads();
        if (cg == 0) ys[f] = (s + red[0][f] + red[1][f] + red[2][f]) * invD;
    }
    __syncthreads();

    {   // partial attn: 512 threads = 64 d x 8 f-parts of 16; batched loads
        int d = t & 63, part = t >> 6;
        const float* wv = Wv + (size_t)(fh * 128 + part * 16) * PROJ + h * DD + d;
        const float* yf = ys + part * 16;
        float w[16];
        #pragma unroll
        for (int f = 0; f < 16; ++f) w[f] = wv[(size_t)f * PROJ];
        float a = 0.f;
        #pragma unroll
        for (int f = 0; f < 16; ++f) a += yf[f] * w[f];
        ared[part][d] = a;
    }
    __syncthreads();
    if (t < DD) {
        float s = 0.f;
        #pragma unroll
        for (int p = 0; p < 8; ++p) s += ared[p][t];
        attn_s[t] = s;
    }
    __syncthreads();

    {   // Wo projection: 512 threads = 64 j4 x 8 d-parts of 8
        int j4 = t & 63, dp = t >> 6;
        const float4* wo4 = (const float4*)Wo + (size_t)(h * DD + dp * 8) * 64 + j4;
        const float* ad = attn_s + dp * 8;
        float4 w[8];
        #pragma unroll
        for (int i = 0; i < 8; ++i) w[i] = wo4[(size_t)i * 64];
        float4 acc = make_float4(0.f, 0.f, 0.f, 0.f);
        #pragma unroll
        for (int i = 0; i < 8; ++i) {
            float a = ad[i];
            acc.x += a * w[i].x; acc.y += a * w[i].y;
            acc.z += a * w[i].z; acc.w += a * w[i].w;
        }
        if (dp > 0) red4[dp - 1][j4] = acc;
        __syncthreads();
        if (dp == 0) {
            #pragma unroll
            for (int g = 0; g < 7; ++g) {
                float4 o = red4[g][j4];
                acc.x += o.x; acc.y += o.y; acc.z += o.z; acc.w += o.w;
            }
            float4* op = (float4*)g_op + (size_t)(b * 16 + h * 2 + fh) * 64 + j4;
            *op = acc;
        }
    }

    // last-block-per-b finalization (deterministic fixed-order sum)
    __syncthreads();
    if (t == 0) {
        __threadfence();
        isLast = (atomicAdd(&g_pcnt2[b], 1u) == 15u) ? 1 : 0;
    }
    __syncthreads();
    if (isLast && t < FF) {
        const float* pp = g_op + (size_t)b * 16 * FF + t;
        float v[16];
        #pragma unroll
        for (int p = 0; p < 16; ++p) v[p] = pp[(size_t)p * FF];
        float s = bo[t];
        #pragma unroll
        for (int p = 0; p < 16; ++p) s += v[p];
        out[(size_t)b * FF + t] = s;
    }
}

// -------------------------------------------------------------------------
extern "C" void kernel_launch(void* const* d_in, const int* in_sizes, int n_in,
                              void* d_out, int out_size) {
    const float* x  = (const float*)d_in[0];
    const float* Wq = (const float*)d_in[1];
    const float* Wk = (const float*)d_in[2];
    const float* Wv = (const float*)d_in[3];
    const float* Wo = (const float*)d_in[4];
    const float* bo = (const float*)d_in[5];
    float* out = (float*)d_out;

    k_main<<<BB * NSC, 256>>>(x, Wq, Wk);
    k_proj<<<BB * HH * 2, 512>>>(Wv, Wo, bo, out);
}

// round 14
// speedup vs baseline: 1.0076x; 1.0076x over previous
#include <cuda_runtime.h>
#include <cuda_bf16.h>

// Problem constants
#define BB 8
#define SS 2048
#define FF 256
#define HH 8
#define DD 64
#define PROJ 512            // HH*DD
#define NSC 32              // s-chunks (64 rows each)
#define SCH 64              // rows per chunk

// Scratch (device globals — no allocation allowed)
__device__ float g_p[BB * HH * FF];             // p[b][h][f] = Wk_h @ q_last
__device__ float g_cm[BB * HH * NSC * 2];       // per-chunk (max, sumexp)
__device__ float g_yc[BB * NSC * HH * FF];      // unnormalized chunk sums (2MB)
__device__ float g_attnp[2 * BB * PROJ];        // partial attn (f-halves)

// ---- cp.async helpers (sm_80+; no dest registers, deep pipelining) ------
__device__ __forceinline__ void cp_async16(void* smem_dst, const void* gmem_src) {
    unsigned s = (unsigned)__cvta_generic_to_shared(smem_dst);
    asm volatile("cp.async.cg.shared.global [%0], [%1], 16;" :: "r"(s), "l"(gmem_src));
}
__device__ __forceinline__ void cp_async_commit_wait_all() {
    asm volatile("cp.async.commit_group;\n" "cp.async.wait_group 0;" ::: "memory");
}

// -------------------------------------------------------------------------
// K1: per (b,h): q_h = x[b,S-1,:] @ Wq[:,h*64:+64]; p[b,h,f] = Wk[f,h*64:].q_h
// grid: 64 blocks, 512 threads
// -------------------------------------------------------------------------
__global__ void k_prep(const float* __restrict__ x,
                       const float* __restrict__ Wq,
                       const float* __restrict__ Wk) {
    int blk = blockIdx.x;
    int b = blk >> 3, h = blk & 7;
    int t = threadIdx.x;
    __shared__ float xs[FF];
    __shared__ float qred[8][DD];
    __shared__ float qs[DD];
    __shared__ float qp[2][FF];

    if (t < FF) xs[t] = x[((size_t)b * SS + (SS - 1)) * FF + t];
    __syncthreads();

    {   // q_h[d]: 512 threads = 64 d x 8 f-parts of 32
        int d = t & 63, part = t >> 6;
        const float* wq = Wq + (size_t)(part * 32) * PROJ + h * DD + d;
        const float* xf = xs + part * 32;
        float a = 0.f;
        #pragma unroll
        for (int g = 0; g < 2; ++g) {
            float w[16];
            #pragma unroll
            for (int i = 0; i < 16; ++i) w[i] = wq[(size_t)(g * 16 + i) * PROJ];
            #pragma unroll
            for (int i = 0; i < 16; ++i) a += xf[g * 16 + i] * w[i];
        }
        qred[part][d] = a;
    }
    __syncthreads();
    if (t < DD) {
        float s = 0.f;
        #pragma unroll
        for (int p = 0; p < 8; ++p) s += qred[p][t];
        qs[t] = s;
    }
    __syncthreads();

    {   // p[f]: 512 threads = 256 f x 2 d-halves of 32 (contiguous 128B reads)
        int f = t & 255, dh = t >> 8;
        const float4* wk4 = (const float4*)(Wk + (size_t)f * PROJ + h * DD + dh * 32);
        const float4* q4 = (const float4*)(qs + dh * 32);
        float4 w[8];
        #pragma unroll
        for (int i = 0; i < 8; ++i) w[i] = wk4[i];
        float a = 0.f;
        #pragma unroll
        for (int i = 0; i < 8; ++i) {
            float4 q = q4[i];
            a += w[i].x * q.x + w[i].y * q.y + w[i].z * q.z + w[i].w * q.w;
        }
        qp[dh][f] = a;
    }
    __syncthreads();
    if (t < FF) g_p[(b * HH + h) * FF + t] = qp[0][t] + qp[1][t];
}

// -------------------------------------------------------------------------
// K2: flash pass — one read of x. Per (b, 64-row chunk):
//   Phase A: scores; local stats (m_c, d_c) -> g_cm; ws = exp(sc - m_c)
//   Phase B: yc[h][f] = sum_s ws[h][s] * x[s][f]  (x re-read from L1)
// grid: BB*NSC = 256 blocks, 256 threads
// -------------------------------------------------------------------------
__global__ void k_flash(const float* __restrict__ x) {
    int blk = blockIdx.x;
    int b = blk >> 5;
    int chunk = blk & 31;
    int t = threadIdx.x;
    int warp = t >> 5, lane = t & 31;
    __shared__ float ps[HH * FF];       // 8KB
    __shared__ float sbuf[HH][SCH];     // 2KB
    __shared__ float ws[HH][SCH];       // 2KB
    __shared__ float mh[HH];

    for (int i = t; i < HH * FF; i += 256) ps[i] = g_p[b * HH * FF + i];
    __syncthreads();

    const float4* ps4 = (const float4*)ps;
    const float4* xr_base = (const float4*)(x + ((size_t)b * SS + chunk * SCH) * FF);

    // ---- Phase A: scores ----
    #pragma unroll
    for (int it = 0; it < 2; ++it) {
        int r0 = it * 32 + warp * 4;
        const float4* xr = xr_base + (size_t)r0 * 64;

        float4 a[4], c[4];
        #pragma unroll
        for (int r = 0; r < 4; ++r) {
            a[r] = xr[r * 64 + lane];
            c[r] = xr[r * 64 + 32 + lane];
        }

        #pragma unroll
        for (int r = 0; r < 4; ++r) {
            float dot[HH];
            #pragma unroll
            for (int h = 0; h < HH; ++h) {
                float4 pa = ps4[h * 64 + lane];
                float4 pc = ps4[h * 64 + 32 + lane];
                dot[h] = a[r].x * pa.x + a[r].y * pa.y + a[r].z * pa.z + a[r].w * pa.w
                       + c[r].x * pc.x + c[r].y * pc.y + c[r].z * pc.z + c[r].w * pc.w;
            }
            #pragma unroll
            for (int h = 0; h < HH; ++h) {
                #pragma unroll
                for (int o = 16; o; o >>= 1)
                    dot[h] += __shfl_xor_sync(0xFFFFFFFFu, dot[h], o);
            }
            if (lane == 0) {
                #pragma unroll
                for (int h = 0; h < HH; ++h)
                    sbuf[h][r0 + r] = dot[h] * 0.125f;
            }
        }
    }
    __syncthreads();

    // ---- local stats: warp h handles head h ----
    if (warp < HH) {
        int h = warp;
        float v0 = sbuf[h][lane], v1 = sbuf[h][lane + 32];
        float m = fmaxf(v0, v1);
        #pragma unroll
        for (int o = 16; o; o >>= 1) m = fmaxf(m, __shfl_xor_sync(0xFFFFFFFFu, m, o));
        float s = __expf(v0 - m) + __expf(v1 - m);
        #pragma unroll
        for (int o = 16; o; o >>= 1) s += __shfl_xor_sync(0xFFFFFFFFu, s, o);
        if (lane == 0) {
            int idx = ((b * HH + h) * NSC + chunk) * 2;
            g_cm[idx] = m;
            g_cm[idx + 1] = s;
            mh[h] = m;
        }
    }
    __syncthreads();

    // ---- unnormalized weights ----
    #pragma unroll
    for (int i = 0; i < 2; ++i) {
        int e = t + i * 256;
        int h = e >> 6, s = e & 63;
        ws[h][s] = __expf(sbuf[h][s] - mh[h]);
    }
    __syncthreads();

    // ---- Phase B: weighted sum (x hits L1); head-pair per thread ----
    int f4 = t & 63, hp = t >> 6;
    int h0 = hp * 2;
    float4 a0 = make_float4(0.f, 0.f, 0.f, 0.f);
    float4 a1 = make_float4(0.f, 0.f, 0.f, 0.f);

    #pragma unroll 4
    for (int s = 0; s < SCH; ++s) {
        float4 xv = xr_base[(size_t)s * 64 + f4];
        float w0 = ws[h0][s], w1 = ws[h0 + 1][s];
        a0.x += w0 * xv.x; a0.y += w0 * xv.y; a0.z += w0 * xv.z; a0.w += w0 * xv.w;
        a1.x += w1 * xv.x; a1.y += w1 * xv.y; a1.z += w1 * xv.z; a1.w += w1 * xv.w;
    }

    float4* out4 = (float4*)(g_yc + ((size_t)(b * NSC + chunk)) * (HH * FF));
    out4[h0 * 64 + f4] = a0;
    out4[(h0 + 1) * 64 + f4] = a1;
}

// -------------------------------------------------------------------------
// K3: per (b,h,f-half): y[f] = (sum_c exp(m_c-M) yc[c][f]) / D; then
//     partial attn over this f-half: attnp = y_half @ Wv_half
// grid: BB*HH*2 = 128 blocks, 512 threads
// -------------------------------------------------------------------------
__global__ void k_attn(const float* __restrict__ Wv) {
    int blk = blockIdx.x;
    int b = blk >> 4;
    int h = (blk >> 1) & 7;
    int fh = blk & 1;
    int t = threadIdx.x;
    __shared__ float scales[NSC];
    __shared__ float stats[2];
    __shared__ float red[3][128];
    __shared__ float ys[128];
    __shared__ float ared[8][DD];

    if (t < 32) {   // warp 0: global stats + per-chunk scales
        const float* cm = g_cm + (size_t)(b * HH + h) * NSC * 2;
        float m = cm[t * 2], d = cm[t * 2 + 1];
        float M = m;
        #pragma unroll
        for (int o = 16; o; o >>= 1) M = fmaxf(M, __shfl_xor_sync(0xFFFFFFFFu, M, o));
        float e = __expf(m - M);
        scales[t] = e;
        float ds = d * e;
        #pragma unroll
        for (int o = 16; o; o >>= 1) ds += __shfl_xor_sync(0xFFFFFFFFu, ds, o);
        if (t == 0) stats[1] = 1.f / ds;
    }
    __syncthreads();
    float invD = stats[1];

    {   // y-half: 512 threads = 128 f x 4 chunk-groups of 8
        int f = t & 127, cg = t >> 7;
        const float* pp = g_yc + ((size_t)(b * NSC + cg * 8) * HH + h) * FF + fh * 128 + f;
        float v[8];
        #pragma unroll
        for (int c = 0; c < 8; ++c) v[c] = pp[(size_t)c * (HH * FF)];
        float s = 0.f;
        #pragma unroll
        for (int c = 0; c < 8; ++c) s += scales[cg * 8 + c] * v[c];
        if (cg > 0) red[cg - 1][f] = s;
        __syncthreads();
        if (cg == 0) ys[f] = (s + red[0][f] + red[1][f] + red[2][f]) * invD;
    }
    __syncthreads();

    {   // partial attn: 512 threads = 64 d x 8 f-parts of 16
        int d = t & 63, part = t >> 6;
        const float* wv = Wv + (size_t)(fh * 128 + part * 16) * PROJ + h * DD + d;
        const float* yf = ys + part * 16;
        float w[16];
        #pragma unroll
        for (int f = 0; f < 16; ++f) w[f] = wv[(size_t)f * PROJ];
        float a = 0.f;
        #pragma unroll
        for (int f = 0; f < 16; ++f) a += yf[f] * w[f];
        ared[part][d] = a;
    }
    __syncthreads();
    if (t < DD) {
        float s = 0.f;
        #pragma unroll
        for (int p = 0; p < 8; ++p) s += ared[p][t];
        g_attnp[(size_t)fh * (BB * PROJ) + b * PROJ + h * DD + t] = s;
    }
}

// -------------------------------------------------------------------------
// K4: out[b,j] = sum_c attn[b,c] * Wo[c,j] + bo[j]
// grid: BB*16 = 128 blocks (16 j each), 256 threads
// cp.async stages the 512x16 Wo slice into smem (row stride 20 floats: 80B,
// 16B-aligned, <=2-way bank conflicts). No load-serialization possible.
// -------------------------------------------------------------------------
#define WOS_STRIDE 20
__global__ void k_final(const float* __restrict__ Wo,
                        const float* __restrict__ bo,
                        float* __restrict__ out) {
    int blk = blockIdx.x;
    int b = blk >> 4, jblk = blk & 15;
    int t = threadIdx.x;
    __shared__ float wo_s[PROJ * WOS_STRIDE];   // 40KB
    __shared__ float as[PROJ];
    __shared__ float red[16][17];

    // stage Wo[:, jblk*16 : +16]: 512 rows x 64B = 2048 x 16B chunks, 8/thread
    #pragma unroll
    for (int i = 0; i < 8; ++i) {
        int id = i * 256 + t;
        int row = id >> 2, q = id & 3;
        cp_async16(&wo_s[row * WOS_STRIDE + q * 4],
                   Wo + (size_t)row * FF + jblk * 16 + q * 4);
    }

    // attn vector while copies are in flight
    #pragma unroll
    for (int i = 0; i < 2; ++i) {
        int c = t + i * 256;
        as[c] = g_attnp[b * PROJ + c] + g_attnp[BB * PROJ + b * PROJ + c];
    }

    cp_async_commit_wait_all();
    __syncthreads();

    {   // 256 threads = 16 j x 16 c-parts of 32
        int j = t & 15, cp = t >> 4;
        const float* wp = wo_s + (size_t)(cp * 32) * WOS_STRIDE + j;
        const float* ap = as + cp * 32;
        float a = 0.f;
        #pragma unroll
        for (int c = 0; c < 32; ++c) a += ap[c] * wp[c * WOS_STRIDE];
        red[cp][j] = a;
    }
    __syncthreads();

    if (t < 16) {
        float s = 0.f;
        #pragma unroll
        for (int p = 0; p < 16; ++p) s += red[p][t];
        int j = jblk * 16 + t;
        out[(size_t)b * FF + j] = s + bo[j];
    }
}

// -------------------------------------------------------------------------
extern "C" void kernel_launch(void* const* d_in, const int* in_sizes, int n_in,
                              void* d_out, int out_size) {
    const float* x  = (const float*)d_in[0];
    const float* Wq = (const float*)d_in[1];
    const float* Wk = (const float*)d_in[2];
    const float* Wv = (const float*)d_in[3];
    const float* Wo = (const float*)d_in[4];
    const float* bo = (const float*)d_in[5];
    float* out = (float*)d_out;

    k_prep<<<BB * HH, 512>>>(x, Wq, Wk);
    k_flash<<<BB * NSC, 256>>>(x);
    k_attn<<<BB * HH * 2, 512>>>(Wv);
    k_final<<<BB * 16, 256>>>(Wo, bo, out);
}

// round 15
// speedup vs baseline: 1.0231x; 1.0154x over previous
#include <cuda_runtime.h>
#include <cuda_bf16.h>

// Problem constants
#define BB 8
#define SS 2048
#define FF 256
#define HH 8
#define DD 64
#define PROJ 512            // HH*DD
#define NSC 32              // s-chunks (64 rows each)
#define SCH 64              // rows per chunk

// Scratch (device globals — no allocation allowed)
__device__ float g_p[BB * HH * FF];             // p[b][h][f] = Wk_h @ q_last
__device__ float g_cm[BB * HH * NSC * 2];       // per-chunk (max, sumexp)
__device__ float g_yc[BB * NSC * HH * FF];      // unnormalized chunk sums (2MB)
__device__ float g_op[BB * 16 * FF];            // partial outputs per (h,fh)
__device__ unsigned int g_pcnt2[BB];            // proj-done count; reset in k_prep

// -------------------------------------------------------------------------
// K1: per (b,h): q_h = x[b,S-1,:] @ Wq[:,h*64:+64]; p[b,h,f] = Wk[f,h*64:].q_h
// grid: 64 blocks, 512 threads. Block 0 also resets k_proj's counters.
// -------------------------------------------------------------------------
__global__ void k_prep(const float* __restrict__ x,
                       const float* __restrict__ Wq,
                       const float* __restrict__ Wk) {
    int blk = blockIdx.x;
    int b = blk >> 3, h = blk & 7;
    int t = threadIdx.x;
    __shared__ float xs[FF];
    __shared__ float qred[8][DD];
    __shared__ float qs[DD];
    __shared__ float qp[2][FF];

    if (blk == 0 && t < BB) g_pcnt2[t] = 0u;   // replay-safe reset for k_proj

    if (t < FF) xs[t] = x[((size_t)b * SS + (SS - 1)) * FF + t];
    __syncthreads();

    {   // q_h[d]: 512 threads = 64 d x 8 f-parts of 32
        int d = t & 63, part = t >> 6;
        const float* wq = Wq + (size_t)(part * 32) * PROJ + h * DD + d;
        const float* xf = xs + part * 32;
        float a = 0.f;
        #pragma unroll
        for (int g = 0; g < 2; ++g) {
            float w[16];
            #pragma unroll
            for (int i = 0; i < 16; ++i) w[i] = wq[(size_t)(g * 16 + i) * PROJ];
            #pragma unroll
            for (int i = 0; i < 16; ++i) a += xf[g * 16 + i] * w[i];
        }
        qred[part][d] = a;
    }
    __syncthreads();
    if (t < DD) {
        float s = 0.f;
        #pragma unroll
        for (int p = 0; p < 8; ++p) s += qred[p][t];
        qs[t] = s;
    }
    __syncthreads();

    {   // p[f]: 512 threads = 256 f x 2 d-halves of 32 (contiguous 128B reads)
        int f = t & 255, dh = t >> 8;
        const float4* wk4 = (const float4*)(Wk + (size_t)f * PROJ + h * DD + dh * 32);
        const float4* q4 = (const float4*)(qs + dh * 32);
        float4 w[8];
        #pragma unroll
        for (int i = 0; i < 8; ++i) w[i] = wk4[i];
        float a = 0.f;
        #pragma unroll
        for (int i = 0; i < 8; ++i) {
            float4 q = q4[i];
            a += w[i].x * q.x + w[i].y * q.y + w[i].z * q.z + w[i].w * q.w;
        }
        qp[dh][f] = a;
    }
    __syncthreads();
    if (t < FF) g_p[(b * HH + h) * FF + t] = qp[0][t] + qp[1][t];
}

// -------------------------------------------------------------------------
// K2: flash pass — one read of x. Per (b, 64-row chunk):
//   Phase A: scores; local stats (m_c, d_c) -> g_cm; ws = exp(sc - m_c)
//   Phase B: thread = (s-half, head-quad, f4): 4 heads x 32 s, half the
//            L1 re-reads of the head-pair layout; single-stage smem combine.
// grid: BB*NSC = 256 blocks, 256 threads
// -------------------------------------------------------------------------
__global__ void k_flash(const float* __restrict__ x) {
    int blk = blockIdx.x;
    int b = blk >> 5;
    int chunk = blk & 31;
    int t = threadIdx.x;
    int warp = t >> 5, lane = t & 31;
    __shared__ float ps[HH * FF];       // 8KB
    __shared__ float sbuf[HH][SCH];     // 2KB
    __shared__ float ws[HH][SCH];       // 2KB
    __shared__ float mh[HH];
    __shared__ float4 redB[HH][64];     // 8KB

    for (int i = t; i < HH * FF; i += 256) ps[i] = g_p[b * HH * FF + i];
    __syncthreads();

    const float4* ps4 = (const float4*)ps;
    const float4* xr_base = (const float4*)(x + ((size_t)b * SS + chunk * SCH) * FF);

    // ---- Phase A: scores ----
    #pragma unroll
    for (int it = 0; it < 2; ++it) {
        int r0 = it * 32 + warp * 4;
        const float4* xr = xr_base + (size_t)r0 * 64;

        float4 a[4], c[4];
        #pragma unroll
        for (int r = 0; r < 4; ++r) {
            a[r] = xr[r * 64 + lane];
            c[r] = xr[r * 64 + 32 + lane];
        }

        #pragma unroll
        for (int r = 0; r < 4; ++r) {
            float dot[HH];
            #pragma unroll
            for (int h = 0; h < HH; ++h) {
                float4 pa = ps4[h * 64 + lane];
                float4 pc = ps4[h * 64 + 32 + lane];
                dot[h] = a[r].x * pa.x + a[r].y * pa.y + a[r].z * pa.z + a[r].w * pa.w
                       + c[r].x * pc.x + c[r].y * pc.y + c[r].z * pc.z + c[r].w * pc.w;
            }
            #pragma unroll
            for (int h = 0; h < HH; ++h) {
                #pragma unroll
                for (int o = 16; o; o >>= 1)
                    dot[h] += __shfl_xor_sync(0xFFFFFFFFu, dot[h], o);
            }
            if (lane == 0) {
                #pragma unroll
                for (int h = 0; h < HH; ++h)
                    sbuf[h][r0 + r] = dot[h] * 0.125f;
            }
        }
    }
    __syncthreads();

    // ---- local stats: warp h handles head h ----
    if (warp < HH) {
        int h = warp;
        float v0 = sbuf[h][lane], v1 = sbuf[h][lane + 32];
        float m = fmaxf(v0, v1);
        #pragma unroll
        for (int o = 16; o; o >>= 1) m = fmaxf(m, __shfl_xor_sync(0xFFFFFFFFu, m, o));
        float s = __expf(v0 - m) + __expf(v1 - m);
        #pragma unroll
        for (int o = 16; o; o >>= 1) s += __shfl_xor_sync(0xFFFFFFFFu, s, o);
        if (lane == 0) {
            int idx = ((b * HH + h) * NSC + chunk) * 2;
            g_cm[idx] = m;
            g_cm[idx + 1] = s;
            mh[h] = m;
        }
    }
    __syncthreads();

    // ---- unnormalized weights ----
    #pragma unroll
    for (int i = 0; i < 2; ++i) {
        int e = t + i * 256;
        int h = e >> 6, s = e & 63;
        ws[h][s] = __expf(sbuf[h][s] - mh[h]);
    }
    __syncthreads();

    // ---- Phase B: weighted sum; (sg = s-half, hg = head-quad, f4) ----
    {
        int f4 = t & 63;
        int hg = (t >> 6) & 1;       // heads hg*4 .. hg*4+3
        int sg = t >> 7;             // s in [sg*32, sg*32+32)
        int h0 = hg * 4;

        float4 acc[4];
        #pragma unroll
        for (int q = 0; q < 4; ++q) acc[q] = make_float4(0.f, 0.f, 0.f, 0.f);

        #pragma unroll 4
        for (int i = 0; i < 32; ++i) {
            int s = sg * 32 + i;
            float4 xv = xr_base[(size_t)s * 64 + f4];
            #pragma unroll
            for (int q = 0; q < 4; ++q) {
                float w = ws[h0 + q][s];
                acc[q].x += w * xv.x; acc[q].y += w * xv.y;
                acc[q].z += w * xv.z; acc[q].w += w * xv.w;
            }
        }

        if (sg == 1) {
            #pragma unroll
            for (int q = 0; q < 4; ++q) redB[h0 + q][f4] = acc[q];
        }
        __syncthreads();
        if (sg == 0) {
            float4* out4 = (float4*)(g_yc + ((size_t)(b * NSC + chunk)) * (HH * FF));
            #pragma unroll
            for (int q = 0; q < 4; ++q) {
                float4 o = redB[h0 + q][f4];
                acc[q].x += o.x; acc[q].y += o.y; acc[q].z += o.z; acc[q].w += o.w;
                out4[(h0 + q) * 64 + f4] = acc[q];
            }
        }
    }
}

// -------------------------------------------------------------------------
// K3: per (b,h,fh): y_half -> @Wv_half -> attn_s[64] -> @Wo -> g_op partial.
//     Last block per b (atomic count == 15) sums 16 partials + bias -> out.
// grid: BB*HH*2 = 128 blocks, 512 threads
// -------------------------------------------------------------------------
__global__ void k_proj(const float* __restrict__ Wv,
                       const float* __restrict__ Wo,
                       const float* __restrict__ bo,
                       float* __restrict__ out) {
    int blk = blockIdx.x;
    int b = blk >> 4;
    int h = (blk >> 1) & 7;
    int fh = blk & 1;
    int t = threadIdx.x;
    __shared__ float scales[NSC];
    __shared__ float stats[1];
    __shared__ float red[3][128];
    __shared__ float ys[128];
    __shared__ float ared[8][DD];
    __shared__ float attn_s[DD];
    __shared__ float4 red4[7][64];      // 7KB
    __shared__ int isLast;

    if (t < 32) {   // warp 0: global stats + per-chunk scales
        const float* cm = g_cm + (size_t)(b * HH + h) * NSC * 2;
        float m = cm[t * 2], d = cm[t * 2 + 1];
        float M = m;
        #pragma unroll
        for (int o = 16; o; o >>= 1) M = fmaxf(M, __shfl_xor_sync(0xFFFFFFFFu, M, o));
        float e = __expf(m - M);
        scales[t] = e;
        float ds = d * e;
        #pragma unroll
        for (int o = 16; o; o >>= 1) ds += __shfl_xor_sync(0xFFFFFFFFu, ds, o);
        if (t == 0) stats[0] = 1.f / ds;
    }
    __syncthreads();
    float invD = stats[0];

    {   // y-half: 512 threads = 128 f x 4 chunk-groups of 8; batched loads
        int f = t & 127, cg = t >> 7;
        const float* pp = g_yc + ((size_t)(b * NSC + cg * 8) * HH + h) * FF + fh * 128 + f;
        float v[8];
        #pragma unroll
        for (int c = 0; c < 8; ++c) v[c] = pp[(size_t)c * (HH * FF)];
        float s = 0.f;
        #pragma unroll
        for (int c = 0; c < 8; ++c) s += scales[cg * 8 + c] * v[c];
        if (cg > 0) red[cg - 1][f] = s;
        __syncthreads();
        if (cg == 0) ys[f] = (s + red[0][f] + red[1][f] + red[2][f]) * invD;
    }
    __syncthreads();

    {   // partial attn: 512 threads = 64 d x 8 f-parts of 16; batched loads
        int d = t & 63, part = t >> 6;
        const float* wv = Wv + (size_t)(fh * 128 + part * 16) * PROJ + h * DD + d;
        const float* yf = ys + part * 16;
        float w[16];
        #pragma unroll
        for (int f = 0; f < 16; ++f) w[f] = wv[(size_t)f * PROJ];
        float a = 0.f;
        #pragma unroll
        for (int f = 0; f < 16; ++f) a += yf[f] * w[f];
        ared[part][d] = a;
    }
    __syncthreads();
    if (t < DD) {
        float s = 0.f;
        #pragma unroll
        for (int p = 0; p < 8; ++p) s += ared[p][t];
        attn_s[t] = s;
    }
    __syncthreads();

    {   // Wo projection: 512 threads = 64 j4 x 8 d-parts of 8
        int j4 = t & 63, dp = t >> 6;
        const float4* wo4 = (const float4*)Wo + (size_t)(h * DD + dp * 8) * 64 + j4;
        const float* ad = attn_s + dp * 8;
        float4 w[8];
        #pragma unroll
        for (int i = 0; i < 8; ++i) w[i] = wo4[(size_t)i * 64];
        float4 acc = make_float4(0.f, 0.f, 0.f, 0.f);
        #pragma unroll
        for (int i = 0; i < 8; ++i) {
            float a = ad[i];
            acc.x += a * w[i].x; acc.y += a * w[i].y;
            acc.z += a * w[i].z; acc.w += a * w[i].w;
        }
        if (dp > 0) red4[dp - 1][j4] = acc;
        __syncthreads();
        if (dp == 0) {
            #pragma unroll
            for (int g = 0; g < 7; ++g) {
                float4 o = red4[g][j4];
                acc.x += o.x; acc.y += o.y; acc.z += o.z; acc.w += o.w;
            }
            float4* op = (float4*)g_op + (size_t)(b * 16 + h * 2 + fh) * 64 + j4;
            *op = acc;
        }
    }

    // last-block-per-b finalization (deterministic fixed-order sum)
    __syncthreads();
    if (t == 0) {
        __threadfence();
        isLast = (atomicAdd(&g_pcnt2[b], 1u) == 15u) ? 1 : 0;
    }
    __syncthreads();
    if (isLast && t < FF) {
        const float* pp = g_op + (size_t)b * 16 * FF + t;
        float v[16];
        #pragma unroll
        for (int p = 0; p < 16; ++p) v[p] = pp[(size_t)p * FF];
        float s = bo[t];
        #pragma unroll
        for (int p = 0; p < 16; ++p) s += v[p];
        out[(size_t)b * FF + t] = s;
    }
}

// -------------------------------------------------------------------------
extern "C" void kernel_launch(void* const* d_in, const int* in_sizes, int n_in,
                              void* d_out, int out_size) {
    const float* x  = (const float*)d_in[0];
    const float* Wq = (const float*)d_in[1];
    const float* Wk = (const float*)d_in[2];
    const float* Wv = (const float*)d_in[3];
    const float* Wo = (const float*)d_in[4];
    const float* bo = (const float*)d_in[5];
    float* out = (float*)d_out;

    k_prep<<<BB * HH, 512>>>(x, Wq, Wk);
    k_flash<<<BB * NSC, 256>>>(x);
    k_proj<<<BB * HH * 2, 512>>>(Wv, Wo, bo, out);
}

// round 16
// speedup vs baseline: 1.0829x; 1.0584x over previous
#include <cuda_runtime.h>
#include <cuda_bf16.h>

// Problem constants
#define BB 8
#define SS 2048
#define FF 256
#define HH 8
#define DD 64
#define PROJ 512            // HH*DD
#define NSC 32              // s-chunks (64 rows each)
#define SCH 64              // rows per chunk

// Scratch (device globals — no allocation allowed)
__device__ float g_p[BB * HH * FF];             // p[b][h][f] = Wk_h @ q_last
__device__ float g_cm[BB * HH * NSC * 2];       // per-chunk (max, sumexp)
__device__ float g_yc[BB * NSC * HH * FF];      // unnormalized chunk sums (2MB)
__device__ float g_op[BB * 16 * FF];            // partial outputs per (h,fh)
__device__ unsigned int g_pcnt2[BB];            // proj-done count; reset in k_prep

// -------------------------------------------------------------------------
// K1: per (b,h,fq): q_h = x[b,S-1,:] @ Wq[:,h*64:+64] (recomputed per fq);
//     p[b,h,f] for f in [fq*64, fq*64+64) = Wk[f, h*64:+64] . q_h
// grid: BB*HH*4 = 256 blocks, 512 threads. Block 0 resets k_proj counters.
// -------------------------------------------------------------------------
__global__ void k_prep(const float* __restrict__ x,
                       const float* __restrict__ Wq,
                       const float* __restrict__ Wk) {
    int blk = blockIdx.x;
    int b = blk >> 5;
    int rest = blk & 31;
    int h = rest >> 2;
    int fq = rest & 3;
    int t = threadIdx.x;
    __shared__ float xs[FF];
    __shared__ float qred[8][DD];
    __shared__ float qs[DD];
    __shared__ float qp[8][DD];

    if (blk == 0 && t < BB) g_pcnt2[t] = 0u;   // replay-safe reset for k_proj

    if (t < FF) xs[t] = x[((size_t)b * SS + (SS - 1)) * FF + t];
    __syncthreads();

    {   // q_h[d]: 512 threads = 64 d x 8 f-parts of 32; batched loads
        int d = t & 63, part = t >> 6;
        const float* wq = Wq + (size_t)(part * 32) * PROJ + h * DD + d;
        const float* xf = xs + part * 32;
        float a = 0.f;
        #pragma unroll
        for (int g = 0; g < 2; ++g) {
            float w[16];
            #pragma unroll
            for (int i = 0; i < 16; ++i) w[i] = wq[(size_t)(g * 16 + i) * PROJ];
            #pragma unroll
            for (int i = 0; i < 16; ++i) a += xf[g * 16 + i] * w[i];
        }
        qred[part][d] = a;
    }
    __syncthreads();
    if (t < DD) {
        float s = 0.f;
        #pragma unroll
        for (int p = 0; p < 8; ++p) s += qred[p][t];
        qs[t] = s;
    }
    __syncthreads();

    {   // p[f] for this quarter: 512 threads = 64 f x 8 d-parts of 8
        int fl = t & 63, dp = t >> 6;
        int f = fq * 64 + fl;
        const float4* wk4 = (const float4*)(Wk + (size_t)f * PROJ + h * DD + dp * 8);
        const float4* q4 = (const float4*)(qs + dp * 8);
        float4 w0 = wk4[0], w1 = wk4[1];
        float4 q0 = q4[0], q1 = q4[1];
        float a = w0.x * q0.x + w0.y * q0.y + w0.z * q0.z + w0.w * q0.w
                + w1.x * q1.x + w1.y * q1.y + w1.z * q1.z + w1.w * q1.w;
        qp[dp][fl] = a;
    }
    __syncthreads();
    if (t < 64) {
        float s = 0.f;
        #pragma unroll
        for (int p = 0; p < 8; ++p) s += qp[p][t];
        g_p[(b * HH + h) * FF + fq * 64 + t] = s;
    }
}

// -------------------------------------------------------------------------
// K2: flash pass — one read of x. Per (b, 64-row chunk):
//   Phase A: scores; local stats (m_c, d_c) -> g_cm; ws = exp(sc - m_c)
//   Phase B: thread = (s-half, head-quad, f4): 4 heads x 32 s.
// grid: BB*NSC = 256 blocks, 256 threads
// -------------------------------------------------------------------------
__global__ void k_flash(const float* __restrict__ x) {
    int blk = blockIdx.x;
    int b = blk >> 5;
    int chunk = blk & 31;
    int t = threadIdx.x;
    int warp = t >> 5, lane = t & 31;
    __shared__ float ps[HH * FF];       // 8KB
    __shared__ float sbuf[HH][SCH];     // 2KB
    __shared__ float ws[HH][SCH];       // 2KB
    __shared__ float mh[HH];
    __shared__ float4 redB[HH][64];     // 8KB

    for (int i = t; i < HH * FF; i += 256) ps[i] = g_p[b * HH * FF + i];
    __syncthreads();

    const float4* ps4 = (const float4*)ps;
    const float4* xr_base = (const float4*)(x + ((size_t)b * SS + chunk * SCH) * FF);

    // ---- Phase A: scores ----
    #pragma unroll
    for (int it = 0; it < 2; ++it) {
        int r0 = it * 32 + warp * 4;
        const float4* xr = xr_base + (size_t)r0 * 64;

        float4 a[4], c[4];
        #pragma unroll
        for (int r = 0; r < 4; ++r) {
            a[r] = xr[r * 64 + lane];
            c[r] = xr[r * 64 + 32 + lane];
        }

        #pragma unroll
        for (int r = 0; r < 4; ++r) {
            float dot[HH];
            #pragma unroll
            for (int h = 0; h < HH; ++h) {
                float4 pa = ps4[h * 64 + lane];
                float4 pc = ps4[h * 64 + 32 + lane];
                dot[h] = a[r].x * pa.x + a[r].y * pa.y + a[r].z * pa.z + a[r].w * pa.w
                       + c[r].x * pc.x + c[r].y * pc.y + c[r].z * pc.z + c[r].w * pc.w;
            }
            #pragma unroll
            for (int h = 0; h < HH; ++h) {
                #pragma unroll
                for (int o = 16; o; o >>= 1)
                    dot[h] += __shfl_xor_sync(0xFFFFFFFFu, dot[h], o);
            }
            if (lane == 0) {
                #pragma unroll
                for (int h = 0; h < HH; ++h)
                    sbuf[h][r0 + r] = dot[h] * 0.125f;
            }
        }
    }
    __syncthreads();

    // ---- local stats: warp h handles head h ----
    if (warp < HH) {
        int h = warp;
        float v0 = sbuf[h][lane], v1 = sbuf[h][lane + 32];
        float m = fmaxf(v0, v1);
        #pragma unroll
        for (int o = 16; o; o >>= 1) m = fmaxf(m, __shfl_xor_sync(0xFFFFFFFFu, m, o));
        float s = __expf(v0 - m) + __expf(v1 - m);
        #pragma unroll
        for (int o = 16; o; o >>= 1) s += __shfl_xor_sync(0xFFFFFFFFu, s, o);
        if (lane == 0) {
            int idx = ((b * HH + h) * NSC + chunk) * 2;
            g_cm[idx] = m;
            g_cm[idx + 1] = s;
            mh[h] = m;
        }
    }
    __syncthreads();

    // ---- unnormalized weights ----
    #pragma unroll
    for (int i = 0; i < 2; ++i) {
        int e = t + i * 256;
        int h = e >> 6, s = e & 63;
        ws[h][s] = __expf(sbuf[h][s] - mh[h]);
    }
    __syncthreads();

    // ---- Phase B: weighted sum; (sg = s-half, hg = head-quad, f4) ----
    {
        int f4 = t & 63;
        int hg = (t >> 6) & 1;
        int sg = t >> 7;
        int h0 = hg * 4;

        float4 acc[4];
        #pragma unroll
        for (int q = 0; q < 4; ++q) acc[q] = make_float4(0.f, 0.f, 0.f, 0.f);

        #pragma unroll 4
        for (int i = 0; i < 32; ++i) {
            int s = sg * 32 + i;
            float4 xv = xr_base[(size_t)s * 64 + f4];
            #pragma unroll
            for (int q = 0; q < 4; ++q) {
                float w = ws[h0 + q][s];
                acc[q].x += w * xv.x; acc[q].y += w * xv.y;
                acc[q].z += w * xv.z; acc[q].w += w * xv.w;
            }
        }

        if (sg == 1) {
            #pragma unroll
            for (int q = 0; q < 4; ++q) redB[h0 + q][f4] = acc[q];
        }
        __syncthreads();
        if (sg == 0) {
            float4* out4 = (float4*)(g_yc + ((size_t)(b * NSC + chunk)) * (HH * FF));
            #pragma unroll
            for (int q = 0; q < 4; ++q) {
                float4 o = redB[h0 + q][f4];
                acc[q].x += o.x; acc[q].y += o.y; acc[q].z += o.z; acc[q].w += o.w;
                out4[(h0 + q) * 64 + f4] = acc[q];
            }
        }
    }
}

// -------------------------------------------------------------------------
// K3: per (b,h,fh): y_half -> @Wv_half -> attn_s[64] -> @Wo -> g_op partial.
//     Last block per b (atomic count == 15) sums 16 partials + bias -> out.
// grid: BB*HH*2 = 128 blocks, 512 threads
// -------------------------------------------------------------------------
__global__ void k_proj(const float* __restrict__ Wv,
                       const float* __restrict__ Wo,
                       const float* __restrict__ bo,
                       float* __restrict__ out) {
    int blk = blockIdx.x;
    int b = blk >> 4;
    int h = (blk >> 1) & 7;
    int fh = blk & 1;
    int t = threadIdx.x;
    __shared__ float scales[NSC];
    __shared__ float stats[1];
    __shared__ float red[3][128];
    __shared__ float ys[128];
    __shared__ float ared[8][DD];
    __shared__ float attn_s[DD];
    __shared__ float4 red4[7][64];      // 7KB
    __shared__ int isLast;

    if (t < 32) {   // warp 0: global stats + per-chunk scales
        const float* cm = g_cm + (size_t)(b * HH + h) * NSC * 2;
        float m = cm[t * 2], d = cm[t * 2 + 1];
        float M = m;
        #pragma unroll
        for (int o = 16; o; o >>= 1) M = fmaxf(M, __shfl_xor_sync(0xFFFFFFFFu, M, o));
        float e = __expf(m - M);
        scales[t] = e;
        float ds = d * e;
        #pragma unroll
        for (int o = 16; o; o >>= 1) ds += __shfl_xor_sync(0xFFFFFFFFu, ds, o);
        if (t == 0) stats[0] = 1.f / ds;
    }
    __syncthreads();
    float invD = stats[0];

    {   // y-half: 512 threads = 128 f x 4 chunk-groups of 8; batched loads
        int f = t & 127, cg = t >> 7;
        const float* pp = g_yc + ((size_t)(b * NSC + cg * 8) * HH + h) * FF + fh * 128 + f;
        float v[8];
        #pragma unroll
        for (int c = 0; c < 8; ++c) v[c] = pp[(size_t)c * (HH * FF)];
        float s = 0.f;
        #pragma unroll
        for (int c = 0; c < 8; ++c) s += scales[cg * 8 + c] * v[c];
        if (cg > 0) red[cg - 1][f] = s;
        __syncthreads();
        if (cg == 0) ys[f] = (s + red[0][f] + red[1][f] + red[2][f]) * invD;
    }
    __syncthreads();

    {   // partial attn: 512 threads = 64 d x 8 f-parts of 16; batched loads
        int d = t & 63, part = t >> 6;
        const float* wv = Wv + (size_t)(fh * 128 + part * 16) * PROJ + h * DD + d;
        const float* yf = ys + part * 16;
        float w[16];
        #pragma unroll
        for (int f = 0; f < 16; ++f) w[f] = wv[(size_t)f * PROJ];
        float a = 0.f;
        #pragma unroll
        for (int f = 0; f < 16; ++f) a += yf[f] * w[f];
        ared[part][d] = a;
    }
    __syncthreads();
    if (t < DD) {
        float s = 0.f;
        #pragma unroll
        for (int p = 0; p < 8; ++p) s += ared[p][t];
        attn_s[t] = s;
    }
    __syncthreads();

    {   // Wo projection: 512 threads = 64 j4 x 8 d-parts of 8
        int j4 = t & 63, dp = t >> 6;
        const float4* wo4 = (const float4*)Wo + (size_t)(h * DD + dp * 8) * 64 + j4;
        const float* ad = attn_s + dp * 8;
        float4 w[8];
        #pragma unroll
        for (int i = 0; i < 8; ++i) w[i] = wo4[(size_t)i * 64];
        float4 acc = make_float4(0.f, 0.f, 0.f, 0.f);
        #pragma unroll
        for (int i = 0; i < 8; ++i) {
            float a = ad[i];
            acc.x += a * w[i].x; acc.y += a * w[i].y;
            acc.z += a * w[i].z; acc.w += a * w[i].w;
        }
        if (dp > 0) red4[dp - 1][j4] = acc;
        __syncthreads();
        if (dp == 0) {
            #pragma unroll
            for (int g = 0; g < 7; ++g) {
                float4 o = red4[g][j4];
                acc.x += o.x; acc.y += o.y; acc.z += o.z; acc.w += o.w;
            }
            float4* op = (float4*)g_op + (size_t)(b * 16 + h * 2 + fh) * 64 + j4;
            *op = acc;
        }
    }

    // last-block-per-b finalization (deterministic fixed-order sum)
    __syncthreads();
    if (t == 0) {
        __threadfence();
        isLast = (atomicAdd(&g_pcnt2[b], 1u) == 15u) ? 1 : 0;
    }
    __syncthreads();
    if (isLast && t < FF) {
        const float* pp = g_op + (size_t)b * 16 * FF + t;
        float v[16];
        #pragma unroll
        for (int p = 0; p < 16; ++p) v[p] = pp[(size_t)p * FF];
        float s = bo[t];
        #pragma unroll
        for (int p = 0; p < 16; ++p) s += v[p];
        out[(size_t)b * FF + t] = s;
    }
}

// -------------------------------------------------------------------------
extern "C" void kernel_launch(void* const* d_in, const int* in_sizes, int n_in,
                              void* d_out, int out_size) {
    const float* x  = (const float*)d_in[0];
    const float* Wq = (const float*)d_in[1];
    const float* Wk = (const float*)d_in[2];
    const float* Wv = (const float*)d_in[3];
    const float* Wo = (const float*)d_in[4];
    const float* bo = (const float*)d_in[5];
    float* out = (float*)d_out;

    k_prep<<<BB * HH * 4, 512>>>(x, Wq, Wk);
    k_flash<<<BB * NSC, 256>>>(x);
    k_proj<<<BB * HH * 2, 512>>>(Wv, Wo, bo, out);
}